// round 8
// baseline (speedup 1.0000x reference)
#include <cuda_runtime.h>
#include <cuda_bf16.h>
#include <cuda_fp16.h>
#include <cstdint>

// ---------------- problem constants ----------------
#define NTOK 2048      // B*S
#define DIN  768       // D
#define NEXP 8         // E
#define DOUT 3072      // O
#define NO   (NTOK*DOUT)

// ---------------- GEMM tiling ----------------
#define BM 128
#define BN 256
#define BK 32                  // fp16 elems per chunk (64B per row)
#define NCH (DIN/BK)           // 24
#define RSTRIDE 80             // smem row stride bytes (conflict-free ldmatrix)
#define NSTAGE 3

// smem layout
#define OFF_TOK 0              // 128 int
#define OFF_GAT 512            // 128 float
#define OFF_ST0 1024
#define AOFFS 0
#define BOFFS (128*RSTRIDE)                 // 10240
#define STAGE_SZ (128*RSTRIDE + 256*RSTRIDE)   // 30720
#define SMEM_SZ (OFF_ST0 + NSTAGE*STAGE_SZ)    // 93184

// ---------------- device scratch ----------------
__device__ int   g_counts[NEXP];
__device__ float g_importance[NEXP];
__device__ int   g_list[NEXP * NTOK];
__device__ float g_gateval[NEXP * NTOK];
__device__ int   g_tokexp[NTOK * 2];
__device__ float g_tokgate[NTOK * 2];

__device__ __align__(256) __half g_xh[NTOK*DIN];
__device__ __align__(256) __half g_cwh[NEXP*DOUT*DIN];   // fp16(expert_w + static_w)

// ---------------- PTX helpers (baseline sm_80+, no 'a' features) ----------
__device__ __forceinline__ uint32_t smem_u32(const void* p) {
    uint32_t a;
    asm("{ .reg .u64 t; cvta.to.shared.u64 t, %1; cvt.u32.u64 %0, t; }"
        : "=r"(a) : "l"(p));
    return a;
}
__device__ __forceinline__ void cpasync16(uint32_t dst, const void* src) {
    asm volatile("cp.async.cg.shared.global [%0], [%1], 16;" :: "r"(dst), "l"(src));
}
#define CP_COMMIT() asm volatile("cp.async.commit_group;" ::: "memory")
#define CP_WAIT(n)  asm volatile("cp.async.wait_group %0;" :: "n"(n) : "memory")

__device__ __forceinline__ void ldsm4(uint32_t* r, uint32_t addr) {
    asm volatile("ldmatrix.sync.aligned.m8n8.x4.shared.b16 {%0,%1,%2,%3}, [%4];"
        : "=r"(r[0]), "=r"(r[1]), "=r"(r[2]), "=r"(r[3]) : "r"(addr));
}
__device__ __forceinline__ void mma16816(float* c, const uint32_t* a,
                                         uint32_t b0, uint32_t b1) {
    asm volatile("mma.sync.aligned.m16n8k16.row.col.f32.f16.f16.f32 "
        "{%0,%1,%2,%3}, {%4,%5,%6,%7}, {%8,%9}, {%0,%1,%2,%3};"
        : "+f"(c[0]), "+f"(c[1]), "+f"(c[2]), "+f"(c[3])
        : "r"(a[0]), "r"(a[1]), "r"(a[2]), "r"(a[3]), "r"(b0), "r"(b1));
}

// ---------------- kernel: zero counters ----------------
__global__ void zero_kernel() {
    int t = threadIdx.x;
    if (t < NEXP) { g_counts[t] = 0; g_importance[t] = 0.0f; }
}

// ---------------- kernel: gating (one WARP per token) ----------------
__global__ __launch_bounds__(256)
void gate_kernel(const float* __restrict__ x, const float* __restrict__ wg) {
    int gw   = (blockIdx.x * 256 + threadIdx.x) >> 5;   // global warp = token
    int lane = threadIdx.x & 31;
    if (gw >= NTOK) return;

    const float4* xr = (const float4*)(x + (size_t)gw * DIN);
    float acc[NEXP];
#pragma unroll
    for (int e = 0; e < NEXP; e++) acc[e] = 0.0f;

#pragma unroll
    for (int it = 0; it < DIN/4/32; it++) {             // 6 iters
        int i = it * 32 + lane;
        float4 v = xr[i];
        const float* w0 = wg + (size_t)(i * 4) * NEXP;
#pragma unroll
        for (int e = 0; e < NEXP; e++)
            acc[e] += v.x * w0[e] + v.y * w0[NEXP + e]
                    + v.z * w0[2*NEXP + e] + v.w * w0[3*NEXP + e];
    }
#pragma unroll
    for (int e = 0; e < NEXP; e++) {
#pragma unroll
        for (int off = 16; off > 0; off >>= 1)
            acc[e] += __shfl_xor_sync(0xffffffffu, acc[e], off);
    }
    if (lane == 0) {
        float best = acc[0], second = -3.4e38f;
        int bi = 0, si = -1;
#pragma unroll
        for (int e = 1; e < NEXP; e++) {
            if (acc[e] > best)        { second = best; si = bi; best = acc[e]; bi = e; }
            else if (acc[e] > second) { second = acc[e]; si = e; }
        }
        float e1 = __expf(second - best);
        float inv = 1.0f / (1.0f + e1);
        float g0 = inv, g1 = e1 * inv;
        atomicAdd(&g_importance[bi], g0);
        atomicAdd(&g_importance[si], g1);
        int p0 = atomicAdd(&g_counts[bi], 1);
        g_list[bi * NTOK + p0] = gw;  g_gateval[bi * NTOK + p0] = g0;
        int p1 = atomicAdd(&g_counts[si], 1);
        g_list[si * NTOK + p1] = gw;  g_gateval[si * NTOK + p1] = g1;
        g_tokexp[2*gw] = bi;  g_tokexp[2*gw+1] = si;
        g_tokgate[2*gw] = g0; g_tokgate[2*gw+1] = g1;
    }
}

// ---------------- fp32x4 -> fp16x4 pack (8B) ----------------
__device__ __forceinline__ uint2 cvt4(const float4 a) {
    __half2 h0 = __floats2half2_rn(a.x, a.y);
    __half2 h1 = __floats2half2_rn(a.z, a.w);
    uint2 r;
    r.x = *(uint32_t*)&h0; r.y = *(uint32_t*)&h1;
    return r;
}

// ---------------- kernel: x -> fp16 (coalesced: warp reads 512B lines) ------
__global__ __launch_bounds__(256)
void split_x_kernel(const float* __restrict__ s) {
    int base = blockIdx.x * 1024;
#pragma unroll
    for (int k = 0; k < 4; k++) {
        int idx = base + k * 256 + threadIdx.x;     // float4 index, coalesced
        float4 v = ((const float4*)s)[idx];
        ((uint2*)g_xh)[idx] = cvt4(v);
    }
}

// ---------------- kernel: fp16(expert_w + static_w), coalesced --------------
__global__ __launch_bounds__(256)
void split_cw_kernel(const float* __restrict__ ew, const float* __restrict__ sw) {
    int base = blockIdx.x * 1024;
#pragma unroll
    for (int k = 0; k < 4; k++) {
        int idx = base + k * 256 + threadIdx.x;     // float4 index, coalesced
        int si = idx % (DOUT*DIN/4);
        float4 e4 = ((const float4*)ew)[idx];
        float4 s4 = ((const float4*)sw)[si];
        float4 v = { e4.x + s4.x, e4.y + s4.y, e4.z + s4.z, e4.w + s4.w };
        ((uint2*)g_cwh)[idx] = cvt4(v);
    }
}

// ---------------- kernel: init y with gated biases (+ fused loss) -----------
__global__ __launch_bounds__(256)
void init_y_kernel(float* __restrict__ y, const float* __restrict__ eb,
                   int out_size) {
    if (blockIdx.x == 0 && blockIdx.y == 0 && threadIdx.x == 0 && out_size > NO) {
        float mi = 0.0f, ml = 0.0f;
#pragma unroll
        for (int e = 0; e < NEXP; e++) { mi += g_importance[e]; ml += (float)g_counts[e]; }
        mi *= (1.0f / NEXP); ml *= (1.0f / NEXP);
        float vi = 0.0f, vl = 0.0f;
#pragma unroll
        for (int e = 0; e < NEXP; e++) {
            float di = g_importance[e] - mi;    vi += di * di;
            float dl = (float)g_counts[e] - ml; vl += dl * dl;
        }
        vi *= (1.0f / (NEXP - 1)); vl *= (1.0f / (NEXP - 1));
        y[NO] = 0.01f * (vi / (mi * mi + 1e-10f) + vl / (ml * ml + 1e-10f));
    }
    int n = blockIdx.y;
    int o = blockIdx.x * 1024 + threadIdx.x * 4;
    int e0 = g_tokexp[2*n], e1 = g_tokexp[2*n+1];
    float g0 = g_tokgate[2*n], g1 = g_tokgate[2*n+1];
    float4 b0 = *(const float4*)(eb + (size_t)e0 * DOUT + o);
    float4 b1 = *(const float4*)(eb + (size_t)e1 * DOUT + o);
    float4 r = { g0*b0.x + g1*b1.x, g0*b0.y + g1*b1.y,
                 g0*b0.z + g1*b1.z, g0*b0.w + g1*b1.w };
    *(float4*)(y + (size_t)n * DOUT + o) = r;
}

// ---------------- kernel: fp16 mma.sync expert GEMM ------------------------
// 256 threads, 8 warps, warp tile 64x64 (2m x 4n), 3-stage cp.async.
__global__ __launch_bounds__(256, 1)
void moe_gemm_mma(float* __restrict__ y) {
    extern __shared__ char sm[];
    uint32_t sb = smem_u32(sm);
    int tid = threadIdx.x, wid = tid >> 5, lane = tid & 31;
    int n0 = blockIdx.x * BN;
    int m0 = blockIdx.y * BM;
    int e  = blockIdx.z;
    int cnt = g_counts[e];
    if (m0 >= cnt) return;

    int* tok_s   = (int*)(sm + OFF_TOK);
    float* gat_s = (float*)(sm + OFF_GAT);
    if (tid < BM) {
        int idx = m0 + tid;
        if (idx < cnt) { tok_s[tid] = g_list[e*NTOK + idx]; gat_s[tid] = g_gateval[e*NTOK + idx]; }
        else           { tok_s[tid] = -1; gat_s[tid] = 0.0f; }
    }
    __syncthreads();

    // ---- cp.async geometry: 6 x 16B per thread per stage ----
    int c  = tid & 3;                 // 16B chunk in 64B row
    int rr = tid >> 2;                // 0..63
    size_t wbase = (size_t)e * DOUT * DIN;
    size_t srcA[2]; uint32_t dstA[2];
#pragma unroll
    for (int i = 0; i < 2; i++) {
        int r = rr + i * 64;
        int t = tok_s[r];
        srcA[i] = (size_t)((t < 0) ? 0 : t) * DIN + c * 8;
        dstA[i] = r * RSTRIDE + c * 16;
    }
    size_t srcB[4]; uint32_t dstB[4];
#pragma unroll
    for (int i = 0; i < 4; i++) {
        int r = rr + i * 64;
        srcB[i] = wbase + (size_t)(n0 + r) * DIN + c * 8;
        dstB[i] = r * RSTRIDE + c * 16;
    }

    auto load_chunk = [&](int ch, uint32_t stg) {
        int off = ch * BK;
        uint32_t s0 = sb + OFF_ST0 + stg;
#pragma unroll
        for (int i = 0; i < 2; i++)
            cpasync16(s0 + AOFFS + dstA[i], g_xh + srcA[i] + off);
#pragma unroll
        for (int i = 0; i < 4; i++)
            cpasync16(s0 + BOFFS + dstB[i], g_cwh + srcB[i] + off);
        CP_COMMIT();
    };

    // ---- ldmatrix per-lane base offsets (warp tile 64x64, 2x4 warps) ----
    int wm = (wid >> 2) * 64;         // 0 or 64
    int wn = (wid & 3) * 64;          // 0,64,128,192
    int mat = lane >> 3, r8 = lane & 7;
    uint32_t aoff = (uint32_t)((wm + (mat & 1) * 8 + r8) * RSTRIDE + (mat >> 1) * 16);
    uint32_t boff = (uint32_t)((wn + ((mat >> 1) & 1) * 8 + r8) * RSTRIDE + (mat & 1) * 16);

    float acc[4][8][4] = {};

    load_chunk(0, 0);
    load_chunk(1, STAGE_SZ);

    uint32_t stg = 0;
    for (int ch = 0; ch < NCH; ch++) {
        if (ch < NCH - 1) { CP_WAIT(1); } else { CP_WAIT(0); }
        __syncthreads();
        if (ch + 2 < NCH) {
            uint32_t nst = stg + 2*STAGE_SZ;
            if (nst >= (uint32_t)NSTAGE*STAGE_SZ) nst -= NSTAGE*STAGE_SZ;
            load_chunk(ch + 2, nst);
        }

        uint32_t aBase = sb + OFF_ST0 + stg + AOFFS + aoff;
        uint32_t bBase = sb + OFF_ST0 + stg + BOFFS + boff;

#pragma unroll
        for (int ks = 0; ks < 2; ks++) {
            uint32_t ah[4][4], bh[4][4];
#pragma unroll
            for (int mi = 0; mi < 4; mi++)
                ldsm4(ah[mi], aBase + mi * (16 * RSTRIDE) + ks * 32);
#pragma unroll
            for (int nt = 0; nt < 4; nt++)
                ldsm4(bh[nt], bBase + nt * (16 * RSTRIDE) + ks * 32);
#pragma unroll
            for (int mi = 0; mi < 4; mi++) {
#pragma unroll
                for (int nj = 0; nj < 8; nj++) {
                    uint32_t h0 = bh[nj >> 1][(nj & 1) * 2];
                    uint32_t h1 = bh[nj >> 1][(nj & 1) * 2 + 1];
                    mma16816(acc[mi][nj], ah[mi], h0, h1);
                }
            }
        }
        stg += STAGE_SZ;
        if (stg >= (uint32_t)NSTAGE*STAGE_SZ) stg = 0;
    }

    // ---- epilogue: y[tok] += g * acc ----
    int t4r = lane >> 2;
    int t4c = (lane & 3) * 2;
#pragma unroll
    for (int mi = 0; mi < 4; mi++) {
#pragma unroll
        for (int half = 0; half < 2; half++) {
            int r = wm + mi * 16 + half * 8 + t4r;
            int tok = tok_s[r];
            if (tok < 0) continue;
            float g = gat_s[r];
            float* yr = y + (size_t)tok * DOUT + n0;
#pragma unroll
            for (int nj = 0; nj < 8; nj++) {
                int cn = wn + nj * 8 + t4c;
                atomicAdd(yr + cn,     g * acc[mi][nj][half*2]);
                atomicAdd(yr + cn + 1, g * acc[mi][nj][half*2+1]);
            }
        }
    }
}

// ---------------- launch ----------------
extern "C" void kernel_launch(void* const* d_in, const int* in_sizes, int n_in,
                              void* d_out, int out_size) {
    const float* x        = (const float*)d_in[0];   // [2048, 768]
    const float* w_gate   = (const float*)d_in[1];   // [768, 8]
    const float* expert_w = (const float*)d_in[2];   // [8, 3072, 768]
    const float* expert_b = (const float*)d_in[3];   // [8, 3072]
    const float* static_w = (const float*)d_in[4];   // [3072, 768]
    float* out = (float*)d_out;

    // One-time host resources (created on the eager correctness call,
    // before graph capture; no device memory involved).
    static cudaStream_t s1 = nullptr;
    static cudaEvent_t evFork = nullptr, evCw = nullptr;
    if (!s1) {
        cudaStreamCreateWithFlags(&s1, cudaStreamNonBlocking);
        cudaEventCreateWithFlags(&evFork, cudaEventDisableTiming);
        cudaEventCreateWithFlags(&evCw, cudaEventDisableTiming);
        cudaFuncSetAttribute(moe_gemm_mma,
                             cudaFuncAttributeMaxDynamicSharedMemorySize, SMEM_SZ);
    }

    // Fork: weight conversion runs concurrently with the gating chain.
    cudaEventRecord(evFork, 0);
    cudaStreamWaitEvent(s1, evFork, 0);
    split_cw_kernel<<<NEXP*DOUT*DIN/4/1024, 256, 0, s1>>>(expert_w, static_w);
    cudaEventRecord(evCw, s1);

    // Main-stream chain.
    zero_kernel<<<1, 32>>>();
    gate_kernel<<<NTOK/8, 256>>>(x, w_gate);
    split_x_kernel<<<NTOK*DIN/4/1024, 256>>>(x);
    dim3 igrid(DOUT/1024, NTOK);             // 3 x 2048
    init_y_kernel<<<igrid, 256>>>(out, expert_b, out_size);

    // Join, then GEMM.
    cudaStreamWaitEvent(0, evCw, 0);
    dim3 egrid(DOUT/BN, NTOK/BM, NEXP);      // 12 x 16 x 8 (early exit on cnt)
    moe_gemm_mma<<<egrid, 256, SMEM_SZ>>>(out);
}

// round 9
// speedup vs baseline: 1.1057x; 1.1057x over previous
#include <cuda_runtime.h>
#include <cuda_bf16.h>
#include <cuda_fp16.h>
#include <cstdint>

// ---------------- problem constants ----------------
#define NTOK 2048      // B*S
#define DIN  768       // D
#define NEXP 8         // E
#define DOUT 3072      // O
#define NO   (NTOK*DOUT)

// ---------------- GEMM tiling ----------------
#define BM 128
#define BN 256
#define BK 32                  // fp16 elems per chunk (64B per row)
#define NCH (DIN/BK)           // 24
#define RSTRIDE 80             // smem row stride bytes (conflict-free ldmatrix)
#define NSTAGE 3

// smem layout
#define OFF_TOK 0              // 128 int
#define OFF_GAT 512            // 128 float
#define OFF_ST0 1024
#define AOFFS 0
#define BOFFS (128*RSTRIDE)                 // 10240
#define STAGE_SZ (128*RSTRIDE + 256*RSTRIDE)   // 30720
#define SMEM_SZ (OFF_ST0 + NSTAGE*STAGE_SZ)    // 93184

// ---------------- device scratch ----------------
__device__ int   g_counts[NEXP];
__device__ float g_importance[NEXP];
__device__ int   g_list[NEXP * NTOK];
__device__ float g_gateval[NEXP * NTOK];
__device__ int   g_tokexp[NTOK * 2];
__device__ float g_tokgate[NTOK * 2];

__device__ __align__(256) __half g_xh[NTOK*DIN];
__device__ __align__(256) __half g_cwh[NEXP*DOUT*DIN];   // fp16(expert_w + static_w)

// ---------------- PTX helpers (baseline sm_80+, no 'a' features) ----------
__device__ __forceinline__ uint32_t smem_u32(const void* p) {
    uint32_t a;
    asm("{ .reg .u64 t; cvta.to.shared.u64 t, %1; cvt.u32.u64 %0, t; }"
        : "=r"(a) : "l"(p));
    return a;
}
__device__ __forceinline__ void cpasync16(uint32_t dst, const void* src) {
    asm volatile("cp.async.cg.shared.global [%0], [%1], 16;" :: "r"(dst), "l"(src));
}
#define CP_COMMIT() asm volatile("cp.async.commit_group;" ::: "memory")
#define CP_WAIT(n)  asm volatile("cp.async.wait_group %0;" :: "n"(n) : "memory")

__device__ __forceinline__ void ldsm4(uint32_t* r, uint32_t addr) {
    asm volatile("ldmatrix.sync.aligned.m8n8.x4.shared.b16 {%0,%1,%2,%3}, [%4];"
        : "=r"(r[0]), "=r"(r[1]), "=r"(r[2]), "=r"(r[3]) : "r"(addr));
}
__device__ __forceinline__ void mma16816(float* c, const uint32_t* a,
                                         uint32_t b0, uint32_t b1) {
    asm volatile("mma.sync.aligned.m16n8k16.row.col.f32.f16.f16.f32 "
        "{%0,%1,%2,%3}, {%4,%5,%6,%7}, {%8,%9}, {%0,%1,%2,%3};"
        : "+f"(c[0]), "+f"(c[1]), "+f"(c[2]), "+f"(c[3])
        : "r"(a[0]), "r"(a[1]), "r"(a[2]), "r"(a[3]), "r"(b0), "r"(b1));
}

// ---------------- kernel: zero counters ----------------
__global__ void zero_kernel() {
    int t = threadIdx.x;
    if (t < NEXP) { g_counts[t] = 0; g_importance[t] = 0.0f; }
}

// ---------------- kernel: gating (one WARP per token) ----------------
__global__ __launch_bounds__(256)
void gate_kernel(const float* __restrict__ x, const float* __restrict__ wg) {
    int gw   = (blockIdx.x * 256 + threadIdx.x) >> 5;   // global warp = token
    int lane = threadIdx.x & 31;
    if (gw >= NTOK) return;

    const float4* xr = (const float4*)(x + (size_t)gw * DIN);
    float acc[NEXP];
#pragma unroll
    for (int e = 0; e < NEXP; e++) acc[e] = 0.0f;

#pragma unroll
    for (int it = 0; it < DIN/4/32; it++) {             // 6 iters
        int i = it * 32 + lane;
        float4 v = xr[i];
        const float* w0 = wg + (size_t)(i * 4) * NEXP;
#pragma unroll
        for (int e = 0; e < NEXP; e++)
            acc[e] += v.x * w0[e] + v.y * w0[NEXP + e]
                    + v.z * w0[2*NEXP + e] + v.w * w0[3*NEXP + e];
    }
#pragma unroll
    for (int e = 0; e < NEXP; e++) {
#pragma unroll
        for (int off = 16; off > 0; off >>= 1)
            acc[e] += __shfl_xor_sync(0xffffffffu, acc[e], off);
    }
    if (lane == 0) {
        float best = acc[0], second = -3.4e38f;
        int bi = 0, si = -1;
#pragma unroll
        for (int e = 1; e < NEXP; e++) {
            if (acc[e] > best)        { second = best; si = bi; best = acc[e]; bi = e; }
            else if (acc[e] > second) { second = acc[e]; si = e; }
        }
        float e1 = __expf(second - best);
        float inv = 1.0f / (1.0f + e1);
        float g0 = inv, g1 = e1 * inv;
        atomicAdd(&g_importance[bi], g0);
        atomicAdd(&g_importance[si], g1);
        int p0 = atomicAdd(&g_counts[bi], 1);
        g_list[bi * NTOK + p0] = gw;  g_gateval[bi * NTOK + p0] = g0;
        int p1 = atomicAdd(&g_counts[si], 1);
        g_list[si * NTOK + p1] = gw;  g_gateval[si * NTOK + p1] = g1;
        g_tokexp[2*gw] = bi;  g_tokexp[2*gw+1] = si;
        g_tokgate[2*gw] = g0; g_tokgate[2*gw+1] = g1;
    }
}

// ---------------- fp32x4 -> fp16x4 pack (8B) ----------------
__device__ __forceinline__ uint2 cvt4(const float4 a) {
    __half2 h0 = __floats2half2_rn(a.x, a.y);
    __half2 h1 = __floats2half2_rn(a.z, a.w);
    uint2 r;
    r.x = *(uint32_t*)&h0; r.y = *(uint32_t*)&h1;
    return r;
}

// ---------------- kernel: x -> fp16 (1 float4/thread, max parallelism) ------
__global__ __launch_bounds__(256)
void split_x_kernel(const float* __restrict__ s) {
    int idx = blockIdx.x * 256 + threadIdx.x;          // float4 index
    float4 v = ((const float4*)s)[idx];
    ((uint2*)g_xh)[idx] = cvt4(v);
}

// ---------------- kernel: fp16(expert_w + static_w), 1 float4/thread --------
__global__ __launch_bounds__(256)
void split_cw_kernel(const float* __restrict__ ew, const float* __restrict__ sw) {
    int idx = blockIdx.x * 256 + threadIdx.x;          // float4 index
    int si = idx % (DOUT*DIN/4);
    float4 e4 = ((const float4*)ew)[idx];
    float4 s4 = ((const float4*)sw)[si];
    float4 v = { e4.x + s4.x, e4.y + s4.y, e4.z + s4.z, e4.w + s4.w };
    ((uint2*)g_cwh)[idx] = cvt4(v);
}

// ---------------- kernel: init y with gated biases (+ fused loss) -----------
__global__ __launch_bounds__(256)
void init_y_kernel(float* __restrict__ y, const float* __restrict__ eb,
                   int out_size) {
    if (blockIdx.x == 0 && blockIdx.y == 0 && threadIdx.x == 0 && out_size > NO) {
        float mi = 0.0f, ml = 0.0f;
#pragma unroll
        for (int e = 0; e < NEXP; e++) { mi += g_importance[e]; ml += (float)g_counts[e]; }
        mi *= (1.0f / NEXP); ml *= (1.0f / NEXP);
        float vi = 0.0f, vl = 0.0f;
#pragma unroll
        for (int e = 0; e < NEXP; e++) {
            float di = g_importance[e] - mi;    vi += di * di;
            float dl = (float)g_counts[e] - ml; vl += dl * dl;
        }
        vi *= (1.0f / (NEXP - 1)); vl *= (1.0f / (NEXP - 1));
        y[NO] = 0.01f * (vi / (mi * mi + 1e-10f) + vl / (ml * ml + 1e-10f));
    }
    int n = blockIdx.y;
    int o = blockIdx.x * 1024 + threadIdx.x * 4;
    int e0 = g_tokexp[2*n], e1 = g_tokexp[2*n+1];
    float g0 = g_tokgate[2*n], g1 = g_tokgate[2*n+1];
    float4 b0 = *(const float4*)(eb + (size_t)e0 * DOUT + o);
    float4 b1 = *(const float4*)(eb + (size_t)e1 * DOUT + o);
    float4 r = { g0*b0.x + g1*b1.x, g0*b0.y + g1*b1.y,
                 g0*b0.z + g1*b1.z, g0*b0.w + g1*b1.w };
    *(float4*)(y + (size_t)n * DOUT + o) = r;
}

// ---------------- kernel: fp16 mma.sync expert GEMM ------------------------
// 256 threads, 8 warps, warp tile 64x64 (2m x 4n), 3-stage cp.async.
__global__ __launch_bounds__(256, 1)
void moe_gemm_mma(float* __restrict__ y) {
    extern __shared__ char sm[];
    uint32_t sb = smem_u32(sm);
    int tid = threadIdx.x, wid = tid >> 5, lane = tid & 31;
    int n0 = blockIdx.x * BN;
    int m0 = blockIdx.y * BM;
    int e  = blockIdx.z;
    int cnt = g_counts[e];
    if (m0 >= cnt) return;

    int* tok_s   = (int*)(sm + OFF_TOK);
    float* gat_s = (float*)(sm + OFF_GAT);
    if (tid < BM) {
        int idx = m0 + tid;
        if (idx < cnt) { tok_s[tid] = g_list[e*NTOK + idx]; gat_s[tid] = g_gateval[e*NTOK + idx]; }
        else           { tok_s[tid] = -1; gat_s[tid] = 0.0f; }
    }
    __syncthreads();

    // ---- cp.async geometry: 6 x 16B per thread per stage ----
    int c  = tid & 3;                 // 16B chunk in 64B row
    int rr = tid >> 2;                // 0..63
    size_t wbase = (size_t)e * DOUT * DIN;
    size_t srcA[2]; uint32_t dstA[2];
#pragma unroll
    for (int i = 0; i < 2; i++) {
        int r = rr + i * 64;
        int t = tok_s[r];
        srcA[i] = (size_t)((t < 0) ? 0 : t) * DIN + c * 8;
        dstA[i] = r * RSTRIDE + c * 16;
    }
    size_t srcB[4]; uint32_t dstB[4];
#pragma unroll
    for (int i = 0; i < 4; i++) {
        int r = rr + i * 64;
        srcB[i] = wbase + (size_t)(n0 + r) * DIN + c * 8;
        dstB[i] = r * RSTRIDE + c * 16;
    }

    auto load_chunk = [&](int ch, uint32_t stg) {
        int off = ch * BK;
        uint32_t s0 = sb + OFF_ST0 + stg;
#pragma unroll
        for (int i = 0; i < 2; i++)
            cpasync16(s0 + AOFFS + dstA[i], g_xh + srcA[i] + off);
#pragma unroll
        for (int i = 0; i < 4; i++)
            cpasync16(s0 + BOFFS + dstB[i], g_cwh + srcB[i] + off);
        CP_COMMIT();
    };

    // ---- ldmatrix per-lane base offsets (warp tile 64x64, 2x4 warps) ----
    int wm = (wid >> 2) * 64;         // 0 or 64
    int wn = (wid & 3) * 64;          // 0,64,128,192
    int mat = lane >> 3, r8 = lane & 7;
    uint32_t aoff = (uint32_t)((wm + (mat & 1) * 8 + r8) * RSTRIDE + (mat >> 1) * 16);
    uint32_t boff = (uint32_t)((wn + ((mat >> 1) & 1) * 8 + r8) * RSTRIDE + (mat & 1) * 16);

    float acc[4][8][4] = {};

    load_chunk(0, 0);
    load_chunk(1, STAGE_SZ);

    uint32_t stg = 0;
    for (int ch = 0; ch < NCH; ch++) {
        if (ch < NCH - 1) { CP_WAIT(1); } else { CP_WAIT(0); }
        __syncthreads();
        if (ch + 2 < NCH) {
            uint32_t nst = stg + 2*STAGE_SZ;
            if (nst >= (uint32_t)NSTAGE*STAGE_SZ) nst -= NSTAGE*STAGE_SZ;
            load_chunk(ch + 2, nst);
        }

        uint32_t aBase = sb + OFF_ST0 + stg + AOFFS + aoff;
        uint32_t bBase = sb + OFF_ST0 + stg + BOFFS + boff;

#pragma unroll
        for (int ks = 0; ks < 2; ks++) {
            uint32_t ah[4][4], bh[4][4];
#pragma unroll
            for (int mi = 0; mi < 4; mi++)
                ldsm4(ah[mi], aBase + mi * (16 * RSTRIDE) + ks * 32);
#pragma unroll
            for (int nt = 0; nt < 4; nt++)
                ldsm4(bh[nt], bBase + nt * (16 * RSTRIDE) + ks * 32);
#pragma unroll
            for (int mi = 0; mi < 4; mi++) {
#pragma unroll
                for (int nj = 0; nj < 8; nj++) {
                    uint32_t h0 = bh[nj >> 1][(nj & 1) * 2];
                    uint32_t h1 = bh[nj >> 1][(nj & 1) * 2 + 1];
                    mma16816(acc[mi][nj], ah[mi], h0, h1);
                }
            }
        }
        stg += STAGE_SZ;
        if (stg >= (uint32_t)NSTAGE*STAGE_SZ) stg = 0;
    }

    // ---- epilogue: y[tok] += g * acc ----
    int t4r = lane >> 2;
    int t4c = (lane & 3) * 2;
#pragma unroll
    for (int mi = 0; mi < 4; mi++) {
#pragma unroll
        for (int half = 0; half < 2; half++) {
            int r = wm + mi * 16 + half * 8 + t4r;
            int tok = tok_s[r];
            if (tok < 0) continue;
            float g = gat_s[r];
            float* yr = y + (size_t)tok * DOUT + n0;
#pragma unroll
            for (int nj = 0; nj < 8; nj++) {
                int cn = wn + nj * 8 + t4c;
                atomicAdd(yr + cn,     g * acc[mi][nj][half*2]);
                atomicAdd(yr + cn + 1, g * acc[mi][nj][half*2+1]);
            }
        }
    }
}

// ---------------- launch (serial stream; GEMM is graph launch index 5) ------
extern "C" void kernel_launch(void* const* d_in, const int* in_sizes, int n_in,
                              void* d_out, int out_size) {
    const float* x        = (const float*)d_in[0];   // [2048, 768]
    const float* w_gate   = (const float*)d_in[1];   // [768, 8]
    const float* expert_w = (const float*)d_in[2];   // [8, 3072, 768]
    const float* expert_b = (const float*)d_in[3];   // [8, 3072]
    const float* static_w = (const float*)d_in[4];   // [3072, 768]
    float* out = (float*)d_out;

    cudaFuncSetAttribute(moe_gemm_mma, cudaFuncAttributeMaxDynamicSharedMemorySize, SMEM_SZ);

    zero_kernel<<<1, 32>>>();                                    // 0
    gate_kernel<<<NTOK/8, 256>>>(x, w_gate);                     // 1
    split_x_kernel<<<NTOK*DIN/4/256, 256>>>(x);                  // 2 (1536 blocks)
    dim3 igrid(DOUT/1024, NTOK);
    init_y_kernel<<<igrid, 256>>>(out, expert_b, out_size);      // 3
    split_cw_kernel<<<NEXP*DOUT*DIN/4/256, 256>>>(expert_w, static_w); // 4 (18432 blocks)
    dim3 egrid(DOUT/BN, NTOK/BM, NEXP);
    moe_gemm_mma<<<egrid, 256, SMEM_SZ>>>(out);                  // 5
}